// round 1
// baseline (speedup 1.0000x reference)
#include <cuda_runtime.h>
#include <cstdint>

// Problem constants
#define BATCH   4
#define SEQ     2048
#define KB      8           // num blocks
#define DIM     64          // per-block dim
#define CB      1024        // codes per block
#define ROWS    (BATCH*SEQ) // 8192
#define RPB     128         // rows per CTA (1 row / thread)
#define NTILES  (ROWS/RPB)  // 64
#define CHUNK   64          // codes staged in smem per iter
#define NCHUNK  (CB/CHUNK)  // 16

// Output packing (concatenated float32): codes | inds | commits
#define CODES_ELEMS (ROWS*KB*DIM)   // 4194304
#define INDS_OFF    CODES_ELEMS
#define COMMIT_OFF  (CODES_ELEMS + ROWS*KB)  // 4259840

// Scratch (no allocations allowed)
__device__ float g_esq[KB*CB];
__device__ float g_part[KB*NTILES];

// ---- packed f32x2 helpers ----
__device__ __forceinline__ void fma2(unsigned long long& d, unsigned long long a,
                                     unsigned long long b, unsigned long long c) {
    asm("fma.rn.f32x2 %0, %1, %2, %3;" : "=l"(d) : "l"(a), "l"(b), "l"(c));
}
__device__ __forceinline__ unsigned long long add2(unsigned long long a, unsigned long long b) {
    unsigned long long d;
    asm("add.rn.f32x2 %0, %1, %2;" : "=l"(d) : "l"(a), "l"(b));
    return d;
}
__device__ __forceinline__ float pair_sum(unsigned long long s) {
    float lo, hi;
    asm("mov.b64 {%0, %1}, %2;" : "=f"(lo), "=f"(hi) : "l"(s));
    return lo + hi;
}
// packed (-1.0f, -1.0f):   x - e  ==  fma(e, -1, x)
#define NEG1_PACKED 0xBF800000BF800000ULL

// ---------------- kernel 1: per-code squared norms ----------------
__global__ void esq_kernel(const float* __restrict__ cb) {
    int c = blockIdx.x * blockDim.x + threadIdx.x;   // 0..8191 (k*1024+c)
    const float4* p = reinterpret_cast<const float4*>(cb + (size_t)c * DIM);
    float s = 0.f;
#pragma unroll
    for (int i = 0; i < 16; i++) {
        float4 v = p[i];
        s += v.x * v.x + v.y * v.y + v.z * v.z + v.w * v.w;
    }
    g_esq[c] = s;
}

// ---------------- kernel 2: main VQ ----------------
__global__ __launch_bounds__(RPB)
void vq_kernel(const float* __restrict__ x,
               const float* __restrict__ cbook,
               float* __restrict__ out) {
    __shared__ __align__(16) float s_e[CHUNK * DIM];   // 16 KB
    __shared__ float s_esq[CHUNK];
    __shared__ float s_red[RPB];

    const int tile = blockIdx.x;
    const int kb   = blockIdx.y;
    const int t    = threadIdx.x;
    const int row  = tile * RPB + t;

    // load this thread's x row (64 floats = 32 packed pairs), pre-packed via 128b loads
    const ulonglong2* xp =
        reinterpret_cast<const ulonglong2*>(x + (size_t)row * (KB * DIM) + kb * DIM);
    unsigned long long xr[32];
#pragma unroll
    for (int i = 0; i < 16; i++) {
        ulonglong2 v = xp[i];
        xr[2 * i] = v.x;
        xr[2 * i + 1] = v.y;
    }

    const float* cbk = cbook + (size_t)kb * CB * DIM;

    float best = 3.4e38f;
    int   bidx = 0;

    for (int ch = 0; ch < NCHUNK; ch++) {
        // stage 64 codes (4096 floats) into smem: 128 threads x 8 float4
        const float4* src = reinterpret_cast<const float4*>(cbk + (size_t)ch * CHUNK * DIM);
        float4* dst = reinterpret_cast<float4*>(s_e);
#pragma unroll
        for (int i = 0; i < 8; i++) dst[t + i * RPB] = src[t + i * RPB];
        if (t < CHUNK) s_esq[t] = g_esq[kb * CB + ch * CHUNK + t];
        __syncthreads();

#pragma unroll 2
        for (int c = 0; c < CHUNK; c++) {
            const ulonglong2* ep = reinterpret_cast<const ulonglong2*>(s_e + c * DIM);
            unsigned long long a0 = 0ull, a1 = 0ull, a2 = 0ull, a3 = 0ull;
#pragma unroll
            for (int i = 0; i < 8; i++) {
                ulonglong2 e01 = ep[2 * i];
                ulonglong2 e23 = ep[2 * i + 1];
                fma2(a0, xr[4 * i + 0], e01.x, a0);
                fma2(a1, xr[4 * i + 1], e01.y, a1);
                fma2(a2, xr[4 * i + 2], e23.x, a2);
                fma2(a3, xr[4 * i + 3], e23.y, a3);
            }
            float dot = pair_sum(add2(add2(a0, a1), add2(a2, a3)));
            float score = fmaf(-2.0f, dot, s_esq[c]);
            if (score < best) { best = score; bidx = ch * CHUNK + c; }
        }
        __syncthreads();
    }

    // ---- epilogue: write index, gather winning code, commit loss ----
    out[INDS_OFF + (size_t)row * KB + kb] = (float)bidx;

    const ulonglong2* gp = reinterpret_cast<const ulonglong2*>(cbk + (size_t)bidx * DIM);
    ulonglong2* op =
        reinterpret_cast<ulonglong2*>(out + (size_t)row * (KB * DIM) + kb * DIM);

    unsigned long long csum2 = 0ull;
#pragma unroll
    for (int i = 0; i < 16; i++) {
        ulonglong2 e = gp[i];
        op[i] = e;  // codes output == quantized vector (STE forward value)
        unsigned long long d0, d1;
        fma2(d0, e.x, NEG1_PACKED, xr[2 * i]);      // x - e
        fma2(d1, e.y, NEG1_PACKED, xr[2 * i + 1]);
        fma2(csum2, d0, d0, csum2);
        fma2(csum2, d1, d1, csum2);
    }
    float csum = pair_sum(csum2);

    // deterministic block reduction of commit partial
    s_red[t] = csum;
    __syncthreads();
    for (int s = RPB / 2; s > 0; s >>= 1) {
        if (t < s) s_red[t] += s_red[t + s];
        __syncthreads();
    }
    if (t == 0) g_part[kb * NTILES + tile] = s_red[0];
}

// ---------------- kernel 3: commit reduce ----------------
__global__ void commit_reduce(float* __restrict__ out) {
    __shared__ float s[NTILES];
    const int kb = blockIdx.x;
    const int t  = threadIdx.x;      // 64 threads
    s[t] = g_part[kb * NTILES + t];
    __syncthreads();
    for (int st = NTILES / 2; st > 0; st >>= 1) {
        if (t < st) s[t] += s[t + st];
        __syncthreads();
    }
    if (t == 0)
        out[COMMIT_OFF + kb] = s[0] * (1.0f / (float)(ROWS * DIM));  // mean over (b,n,d)
}

extern "C" void kernel_launch(void* const* d_in, const int* in_sizes, int n_in,
                              void* d_out, int out_size) {
    const float* x  = (const float*)d_in[0];   // [4,2048,512]
    const float* cb = (const float*)d_in[1];   // [8,1024,64]
    float* out = (float*)d_out;

    esq_kernel<<<(KB * CB) / 128, 128>>>(cb);
    dim3 grid(NTILES, KB);
    vq_kernel<<<grid, RPB>>>(x, cb, out);
    commit_reduce<<<KB, NTILES>>>(out);
}

// round 2
// speedup vs baseline: 1.4104x; 1.4104x over previous
#include <cuda_runtime.h>
#include <cstdint>

// Problem constants
#define BATCH   4
#define SEQ     2048
#define KB      8
#define DIM     64
#define CB      1024
#define ROWS    (BATCH*SEQ)      // 8192
#define D_FULL  (KB*DIM)         // 512

// Tiling
#define TILE_R  64               // rows per CTA
#define TILE_C  64               // codes per chunk
#define NCHUNK  (CB/TILE_C)      // 16
#define NTHR    128
#define TR      4                // rows per thread
#define TC      8                // codes per thread
#define XSTRIDE 68               // padded floats per smem row (68 mod 32 = 4)
#define NTILES  (ROWS/TILE_R)    // 128 row tiles

// Output packing (concatenated float32): codes | inds | commits
#define CODES_ELEMS (ROWS*KB*DIM)            // 4194304
#define INDS_OFF    CODES_ELEMS
#define COMMIT_OFF  (CODES_ELEMS + ROWS*KB)  // 4259840

__device__ float g_esq[KB*CB];
__device__ float g_part[KB*NTILES];

// ---- packed f32x2 helpers ----
__device__ __forceinline__ void fma2(unsigned long long& d, unsigned long long a,
                                     unsigned long long b, unsigned long long c) {
    asm("fma.rn.f32x2 %0, %1, %2, %3;" : "=l"(d) : "l"(a), "l"(b), "l"(c));
}
__device__ __forceinline__ float pair_sum(unsigned long long s) {
    float lo, hi;
    asm("mov.b64 {%0, %1}, %2;" : "=f"(lo), "=f"(hi) : "l"(s));
    return lo + hi;
}
__device__ __forceinline__ unsigned long long pack2(float lo, float hi) {
    unsigned long long d;
    asm("mov.b64 %0, {%1, %2};" : "=l"(d) : "f"(lo), "f"(hi));
    return d;
}
__device__ __forceinline__ void combine(float& b, int& i, float ob, int oi) {
    if (ob < b || (ob == b && oi < i)) { b = ob; i = oi; }
}

// ---------------- kernel 1: per-code squared norms ----------------
__global__ void esq_kernel(const float* __restrict__ cb) {
    int c = blockIdx.x * blockDim.x + threadIdx.x;   // 0..8191
    const float4* p = reinterpret_cast<const float4*>(cb + (size_t)c * DIM);
    float s = 0.f;
#pragma unroll
    for (int i = 0; i < 16; i++) {
        float4 v = p[i];
        s += v.x * v.x + v.y * v.y + v.z * v.z + v.w * v.w;
    }
    g_esq[c] = s;
}

// ---------------- kernel 2: main VQ (register-tiled) ----------------
__global__ __launch_bounds__(NTHR, 4)
void vq_kernel(const float* __restrict__ x,
               const float* __restrict__ cbook,
               float* __restrict__ out) {
    __shared__ __align__(16) float xs[TILE_R * XSTRIDE];   // -2*x tile
    __shared__ __align__(16) float es[TILE_C * XSTRIDE];   // e chunk
    __shared__ float s_esq[TILE_C];
    __shared__ float s_bv[2][TILE_R];
    __shared__ int   s_bi[2][TILE_R];
    __shared__ float s_red[NTHR];

    const int tile = blockIdx.x;           // 0..127
    const int kb   = blockIdx.y;           // 0..7
    const int t    = threadIdx.x;
    const int w    = t >> 5;
    const int l    = t & 31;
    const int warp_r = w >> 1;             // 0..1  (row half)
    const int warp_c = w & 1;              // 0..1  (code half)
    const int rg   = l >> 2;               // 0..7  row group
    const int cg   = l & 3;                // 0..3  code group

    const float* cbk = cbook + (size_t)kb * CB * DIM;

    // ---- stage x tile, scaled by -2 ----
    {
        const float4* dummy;
        (void)dummy;
#pragma unroll
        for (int i = 0; i < 8; i++) {
            int f = t + i * NTHR;                  // 0..1023 float4 slots
            int r = f >> 4, c = f & 15;
            const float4* src = reinterpret_cast<const float4*>(
                x + ((size_t)(tile * TILE_R + r) * D_FULL) + kb * DIM);
            float4 v = src[c];
            v.x *= -2.f; v.y *= -2.f; v.z *= -2.f; v.w *= -2.f;
            reinterpret_cast<float4*>(xs)[r * (XSTRIDE / 4) + c] = v;
        }
    }

    // per-thread smem bases
    const float* p_x = xs + (warp_r * 32 + rg) * XSTRIDE;      // +rr*8*XSTRIDE
    const float* p_e = es + (warp_c * 32 + cg) * XSTRIDE;      // +cc*4*XSTRIDE

    float best[TR];
    int   bidx[TR];
#pragma unroll
    for (int rr = 0; rr < TR; rr++) { best[rr] = 3.4e38f; bidx[rr] = 0; }

#pragma unroll 1
    for (int ch = 0; ch < NCHUNK; ch++) {
        // ---- stage e chunk ----
        __syncthreads();   // previous chunk fully consumed
        {
            const float4* src = reinterpret_cast<const float4*>(
                cbk + (size_t)ch * TILE_C * DIM);
#pragma unroll
            for (int i = 0; i < 8; i++) {
                int f = t + i * NTHR;
                int r = f >> 4, c = f & 15;
                reinterpret_cast<float4*>(es)[r * (XSTRIDE / 4) + c] = src[f];
            }
            if (t < TILE_C) s_esq[t] = g_esq[kb * CB + ch * TILE_C + t];
        }
        __syncthreads();

        // ---- init accumulators with e_sq ----
        unsigned long long einit[TC];
#pragma unroll
        for (int cc = 0; cc < TC; cc++)
            einit[cc] = pack2(s_esq[warp_c * 32 + cc * 4 + cg], 0.f);

        unsigned long long acc[TR][TC];
#pragma unroll
        for (int rr = 0; rr < TR; rr++)
#pragma unroll
            for (int cc = 0; cc < TC; cc++) acc[rr][cc] = einit[cc];

        // ---- main FMA loop: 16 iters x 4 floats of d ----
#pragma unroll
        for (int dp = 0; dp < 16; dp++) {
            ulonglong2 xa[TR];
            ulonglong2 eb[TC];
#pragma unroll
            for (int rr = 0; rr < TR; rr++)
                xa[rr] = *reinterpret_cast<const ulonglong2*>(
                    p_x + rr * 8 * XSTRIDE + dp * 4);
#pragma unroll
            for (int cc = 0; cc < TC; cc++)
                eb[cc] = *reinterpret_cast<const ulonglong2*>(
                    p_e + cc * 4 * XSTRIDE + dp * 4);
#pragma unroll
            for (int rr = 0; rr < TR; rr++)
#pragma unroll
                for (int cc = 0; cc < TC; cc++) {
                    fma2(acc[rr][cc], xa[rr].x, eb[cc].x, acc[rr][cc]);
                    fma2(acc[rr][cc], xa[rr].y, eb[cc].y, acc[rr][cc]);
                }
        }

        // ---- score + running argmin (codes increase with ch,cc: strict < ok) ----
#pragma unroll
        for (int rr = 0; rr < TR; rr++)
#pragma unroll
            for (int cc = 0; cc < TC; cc++) {
                float s = pair_sum(acc[rr][cc]);
                int gc = ch * TILE_C + warp_c * 32 + cc * 4 + cg;
                if (s < best[rr]) { best[rr] = s; bidx[rr] = gc; }
            }
    }

    // ---- reduce argmin across the 4 code-lanes (bits 0,1 of lane) ----
#pragma unroll
    for (int rr = 0; rr < TR; rr++) {
#pragma unroll
        for (int m = 1; m <= 2; m <<= 1) {
            float ob = __shfl_xor_sync(0xffffffffu, best[rr], m);
            int   oi = __shfl_xor_sync(0xffffffffu, bidx[rr], m);
            combine(best[rr], bidx[rr], ob, oi);
        }
    }
    __syncthreads();   // es no longer needed; reuse barrier for s_bv
    if (cg == 0) {
#pragma unroll
        for (int rr = 0; rr < TR; rr++) {
            int rl = warp_r * 32 + rr * 8 + rg;
            s_bv[warp_c][rl] = best[rr];
            s_bi[warp_c][rl] = bidx[rr];
        }
    }
    __syncthreads();

    // ---- final per-row epilogue (threads 0..63) ----
    float csum = 0.f;
    if (t < TILE_R) {
        float b0 = s_bv[0][t]; int i0 = s_bi[0][t];
        combine(b0, i0, s_bv[1][t], s_bi[1][t]);

        int row_g = tile * TILE_R + t;
        out[INDS_OFF + (size_t)row_g * KB + kb] = (float)i0;

        const float4* ep = reinterpret_cast<const float4*>(cbk + (size_t)i0 * DIM);
        const float4* xp = reinterpret_cast<const float4*>(
            x + (size_t)row_g * D_FULL + kb * DIM);
        float4* op = reinterpret_cast<float4*>(
            out + (size_t)row_g * D_FULL + kb * DIM);
#pragma unroll
        for (int i = 0; i < 16; i++) {
            float4 e = ep[i];
            float4 xv = xp[i];
            op[i] = e;
            float dx = xv.x - e.x, dy = xv.y - e.y,
                  dz = xv.z - e.z, dw = xv.w - e.w;
            csum += dx * dx + dy * dy + dz * dz + dw * dw;
        }
    }

    // deterministic block reduction of commit partial
    s_red[t] = csum;
    __syncthreads();
    for (int s = NTHR / 2; s > 0; s >>= 1) {
        if (t < s) s_red[t] += s_red[t + s];
        __syncthreads();
    }
    if (t == 0) g_part[kb * NTILES + tile] = s_red[0];
}

// ---------------- kernel 3: commit reduce ----------------
__global__ void commit_reduce(float* __restrict__ out) {
    __shared__ float s[NTILES];
    const int kb = blockIdx.x;
    const int t  = threadIdx.x;      // 128 threads
    s[t] = g_part[kb * NTILES + t];
    __syncthreads();
    for (int st = NTILES / 2; st > 0; st >>= 1) {
        if (t < st) s[t] += s[t + st];
        __syncthreads();
    }
    if (t == 0)
        out[COMMIT_OFF + kb] = s[0] * (1.0f / (float)(ROWS * DIM));
}

extern "C" void kernel_launch(void* const* d_in, const int* in_sizes, int n_in,
                              void* d_out, int out_size) {
    const float* x  = (const float*)d_in[0];   // [4,2048,512]
    const float* cb = (const float*)d_in[1];   // [8,1024,64]
    float* out = (float*)d_out;

    esq_kernel<<<(KB * CB) / 128, 128>>>(cb);
    dim3 grid(NTILES, KB);
    vq_kernel<<<grid, NTHR>>>(x, cb, out);
    commit_reduce<<<KB, NTILES>>>(out);
}

// round 5
// speedup vs baseline: 2.1396x; 1.5170x over previous
#include <cuda_runtime.h>
#include <cuda_fp16.h>
#include <cstdint>

// ---------------- problem constants ----------------
#define KB      8
#define DIM     64
#define CB      1024
#define ROWS    8192
#define D_FULL  512
#define MT      128              // rows per CTA
#define NMT     (ROWS/MT)        // 64
#define NTHR    256
#define NCHUNK  8                // code chunks of 128

#define CODES_ELEMS (ROWS*KB*DIM)            // 4194304
#define INDS_OFF    CODES_ELEMS
#define COMMIT_OFF  (CODES_ELEMS + ROWS*KB)  // 4259840

// ---------------- device scratch ----------------
__device__ float  g_esq[KB*CB];
__device__ float  g_part[KB*NMT];
__device__ __half g_Bh[(size_t)KB*CB*DIM];   // 1 MB
__device__ __half g_Bl[(size_t)KB*CB*DIM];   // 1 MB

// ---------------- smem layout (bytes, dynamic) ----------------
#define SM_ESQ   0                 // 4096
#define SM_AH    4096              // 16384
#define SM_AL    20480             // 16384
#define SM_BH    36864             // 16384
#define SM_BL    53248             // 16384
#define SM_MB1   69632             // 2*128 floats
#define SM_MI1   70656
#define SM_MB2   71680
#define SM_MI2   72704
#define SM_RED   73728             // 256 floats
#define SM_TOTAL 74752

#define SWZ(bo) ((bo) ^ (((bo) >> 3) & 0x70))

// ---------------- helpers ----------------
__device__ __forceinline__ uint32_t smem_u32(const void* p) {
    uint32_t a;
    asm("{ .reg .u64 t; cvta.to.shared.u64 t, %1; cvt.u32.u64 %0, t; }" : "=r"(a) : "l"(p));
    return a;
}
__device__ __forceinline__ void ldsm_x4(uint32_t& r0, uint32_t& r1,
                                        uint32_t& r2, uint32_t& r3, uint32_t addr) {
    asm volatile("ldmatrix.sync.aligned.m8n8.x4.shared.b16 {%0,%1,%2,%3}, [%4];"
                 : "=r"(r0), "=r"(r1), "=r"(r2), "=r"(r3) : "r"(addr));
}
__device__ __forceinline__ void mma16816(float* c, const uint32_t* a, const uint32_t* b) {
    asm volatile("mma.sync.aligned.m16n8k16.row.col.f32.f16.f16.f32 "
                 "{%0,%1,%2,%3}, {%4,%5,%6,%7}, {%8,%9}, {%0,%1,%2,%3};"
                 : "+f"(c[0]), "+f"(c[1]), "+f"(c[2]), "+f"(c[3])
                 : "r"(a[0]), "r"(a[1]), "r"(a[2]), "r"(a[3]), "r"(b[0]), "r"(b[1]));
}
__device__ __forceinline__ void ins2(float& B1, int& I1, float& B2, int& I2,
                                     float v, int i) {
    if (v < B1 || (v == B1 && i < I1)) { B2 = B1; I2 = I1; B1 = v; I1 = i; }
    else if (v < B2 || (v == B2 && i < I2)) { B2 = v; I2 = i; }
}
__device__ __forceinline__ uint32_t pack_h2(float a, float b) {
    __half2 h = __floats2half2_rn(a, b);
    return *reinterpret_cast<uint32_t*>(&h);
}

// ---------------- kernel: exact per-code squared norms ----------------
__global__ void esq_kernel(const float* __restrict__ cb) {
    int c = blockIdx.x * blockDim.x + threadIdx.x;   // 0..8191
    const float4* p = reinterpret_cast<const float4*>(cb + (size_t)c * DIM);
    float s = 0.f;
#pragma unroll
    for (int i = 0; i < 16; i++) {
        float4 v = p[i];
        s += v.x * v.x + v.y * v.y + v.z * v.z + v.w * v.w;
    }
    g_esq[c] = s;
}

// ---------------- kernel: split codebook into fp16 hi/lo ----------------
__global__ void split_cb_kernel(const float* __restrict__ cb) {
    int i = blockIdx.x * 256 + threadIdx.x;          // 0..524287
    float v = cb[i];
    __half h = __float2half_rn(v);
    g_Bh[i] = h;
    g_Bl[i] = __float2half_rn(v - __half2float(h));
}

// ---------------- main kernel: mma.sync fp16 3-pass + argmin ----------------
__global__ __launch_bounds__(NTHR, 2)
void vq_mma_kernel(const float* __restrict__ x,
                   const float* __restrict__ cbook,
                   float* __restrict__ out) {
    extern __shared__ char smem[];
    const uint32_t sb = smem_u32(smem);
    float* esq_s = reinterpret_cast<float*>(smem + SM_ESQ);

    const int t = threadIdx.x, wid = t >> 5, l = t & 31;
    const int mtb = blockIdx.x, kb = blockIdx.y;
    const int warp_r = wid & 3;          // 4 row groups of 32 rows
    const int warp_c = wid >> 2;         // 2 code halves of 64 codes

    // stage esq (exact fp32)
    for (int i = t; i < CB; i += NTHR) esq_s[i] = g_esq[kb * CB + i];

    // ---- stage A: x tile split to fp16 hi/lo, swizzled ----
    {
        const int r = t >> 1, h = t & 1;
        const float4* src = reinterpret_cast<const float4*>(
            x + (size_t)(mtb * MT + r) * D_FULL + kb * DIM + h * 32);
#pragma unroll
        for (int j = 0; j < 8; j++) {
            float4 v = src[j];
            float h0 = __half2float(__float2half_rn(v.x));
            float h1 = __half2float(__float2half_rn(v.y));
            float h2 = __half2float(__float2half_rn(v.z));
            float h3 = __half2float(__float2half_rn(v.w));
            uint2 uh, ul;
            uh.x = pack_h2(v.x, v.y);          uh.y = pack_h2(v.z, v.w);
            ul.x = pack_h2(v.x - h0, v.y - h1); ul.y = pack_h2(v.z - h2, v.w - h3);
            uint32_t bo = SWZ((uint32_t)(r * 128 + h * 64 + j * 8));
            *reinterpret_cast<uint2*>(smem + SM_AH + bo) = uh;
            *reinterpret_cast<uint2*>(smem + SM_AL + bo) = ul;
        }
    }

    float best1[4], best2[4];
    int   idx1[4], idx2[4];
#pragma unroll
    for (int s = 0; s < 4; s++) { best1[s] = 3.4e38f; best2[s] = 3.4e38f; idx1[s] = 0; idx2[s] = 0; }

#pragma unroll 1
    for (int ch = 0; ch < NCHUNK; ch++) {
        __syncthreads();
        // ---- stage B chunk: 128 codes x 64 halfs (hi + lo) ----
        {
            const uint4* srch = reinterpret_cast<const uint4*>(
                g_Bh + ((size_t)kb * CB + ch * 128) * DIM);
            const uint4* srcl = reinterpret_cast<const uint4*>(
                g_Bl + ((size_t)kb * CB + ch * 128) * DIM);
#pragma unroll
            for (int i = 0; i < 4; i++) {
                int f = t + i * NTHR;                 // 0..1023 16B units
                uint32_t bo = SWZ((uint32_t)f * 16u);
                *reinterpret_cast<uint4*>(smem + SM_BH + bo) = srch[f];
                *reinterpret_cast<uint4*>(smem + SM_BL + bo) = srcl[f];
            }
        }
        __syncthreads();

#pragma unroll 1
        for (int nh = 0; nh < 2; nh++) {              // 2 halves of 32 codes
            float acc[2][4][4];
#pragma unroll
            for (int m = 0; m < 2; m++)
#pragma unroll
                for (int n = 0; n < 4; n++)
#pragma unroll
                    for (int q = 0; q < 4; q++) acc[m][n][q] = 0.f;

#pragma unroll
            for (int pass = 0; pass < 3; pass++) {
                const uint32_t abase = sb + ((pass == 2) ? SM_AL : SM_AH);
                const uint32_t bbase = sb + ((pass == 1) ? SM_BL : SM_BH);
#pragma unroll
                for (int ks = 0; ks < 4; ks++) {
                    uint32_t a[2][4];
#pragma unroll
                    for (int m = 0; m < 2; m++) {
                        int row = warp_r * 32 + m * 16 + (l & 15);
                        uint32_t ad = abase +
                            SWZ((uint32_t)(row * 128 + ks * 32 + (l >> 4) * 16));
                        ldsm_x4(a[m][0], a[m][1], a[m][2], a[m][3], ad);
                    }
                    uint32_t b[4][2];
#pragma unroll
                    for (int np = 0; np < 2; np++) {
                        int crow = warp_c * 64 + nh * 32 + np * 16 +
                                   ((l >> 4) & 1) * 8 + (l & 7);
                        uint32_t bd = bbase +
                            SWZ((uint32_t)(crow * 128 + ks * 32 + ((l >> 3) & 1) * 16));
                        uint32_t r0, r1, r2, r3;
                        ldsm_x4(r0, r1, r2, r3, bd);
                        b[np * 2][0] = r0;     b[np * 2][1] = r1;
                        b[np * 2 + 1][0] = r2; b[np * 2 + 1][1] = r3;
                    }
#pragma unroll
                    for (int m = 0; m < 2; m++)
#pragma unroll
                        for (int n = 0; n < 4; n++)
                            mma16816(acc[m][n], a[m], b[n]);
                }
            }

            // ---- scoring: dist = esq - 2*dot; running top-2 per row slot ----
#pragma unroll
            for (int m = 0; m < 2; m++)
#pragma unroll
                for (int n = 0; n < 4; n++) {
                    int cbase = ch * 128 + warp_c * 64 + nh * 32 + n * 8 + 2 * (l & 3);
                    float e0 = esq_s[cbase], e1 = esq_s[cbase + 1];
                    const int s0 = 2 * m, s1 = 2 * m + 1;
                    float v;
                    v = fmaf(-2.f, acc[m][n][0], e0);
                    if (v < best1[s0]) { best2[s0]=best1[s0]; idx2[s0]=idx1[s0]; best1[s0]=v; idx1[s0]=cbase; }
                    else if (v < best2[s0]) { best2[s0]=v; idx2[s0]=cbase; }
                    v = fmaf(-2.f, acc[m][n][1], e1);
                    if (v < best1[s0]) { best2[s0]=best1[s0]; idx2[s0]=idx1[s0]; best1[s0]=v; idx1[s0]=cbase+1; }
                    else if (v < best2[s0]) { best2[s0]=v; idx2[s0]=cbase+1; }
                    v = fmaf(-2.f, acc[m][n][2], e0);
                    if (v < best1[s1]) { best2[s1]=best1[s1]; idx2[s1]=idx1[s1]; best1[s1]=v; idx1[s1]=cbase; }
                    else if (v < best2[s1]) { best2[s1]=v; idx2[s1]=cbase; }
                    v = fmaf(-2.f, acc[m][n][3], e1);
                    if (v < best1[s1]) { best2[s1]=best1[s1]; idx2[s1]=idx1[s1]; best1[s1]=v; idx1[s1]=cbase+1; }
                    else if (v < best2[s1]) { best2[s1]=v; idx2[s1]=cbase+1; }
                }
        }
    }

    // ---- reduce top-2 across the 4 lanes of each quad (l&3) ----
#pragma unroll
    for (int s = 0; s < 4; s++) {
#pragma unroll
        for (int m = 1; m <= 2; m <<= 1) {
            float ob1 = __shfl_xor_sync(0xffffffffu, best1[s], m);
            int   oi1 = __shfl_xor_sync(0xffffffffu, idx1[s], m);
            float ob2 = __shfl_xor_sync(0xffffffffu, best2[s], m);
            int   oi2 = __shfl_xor_sync(0xffffffffu, idx2[s], m);
            ins2(best1[s], idx1[s], best2[s], idx2[s], ob1, oi1);
            ins2(best1[s], idx1[s], best2[s], idx2[s], ob2, oi2);
        }
    }
    __syncthreads();
    float* mb1 = reinterpret_cast<float*>(smem + SM_MB1);
    int*   mi1 = reinterpret_cast<int*>  (smem + SM_MI1);
    float* mb2 = reinterpret_cast<float*>(smem + SM_MB2);
    int*   mi2 = reinterpret_cast<int*>  (smem + SM_MI2);
    if ((l & 3) == 0) {
#pragma unroll
        for (int s = 0; s < 4; s++) {
            int row = warp_r * 32 + (s >> 1) * 16 + (s & 1) * 8 + (l >> 2);
            mb1[warp_c * 128 + row] = best1[s];  mi1[warp_c * 128 + row] = idx1[s];
            mb2[warp_c * 128 + row] = best2[s];  mi2[warp_c * 128 + row] = idx2[s];
        }
    }
    __syncthreads();

    // ---- per-row epilogue (threads 0..127) ----
    float csum = 0.f;
    if (t < MT) {
        float B1 = mb1[t], B2 = mb2[t];
        int   I1 = mi1[t], I2 = mi2[t];
        ins2(B1, I1, B2, I2, mb1[128 + t], mi1[128 + t]);
        ins2(B1, I1, B2, I2, mb2[128 + t], mi2[128 + t]);

        const int row_g = mtb * MT + t;
        const float4* xp = reinterpret_cast<const float4*>(
            x + (size_t)row_g * D_FULL + kb * DIM);
        float4 xr[16];
#pragma unroll
        for (int i = 0; i < 16; i++) xr[i] = xp[i];

        // near-tie safety: exact fp32 rescore of top-2 (approx err ~1e-5 << 1e-3)
        if (B2 - B1 < 1e-3f) {
            const float* base = cbook + (size_t)kb * CB * DIM;
            float d1 = 0.f, d2 = 0.f;
            const float4* p1 = reinterpret_cast<const float4*>(base + (size_t)I1 * DIM);
            const float4* p2 = reinterpret_cast<const float4*>(base + (size_t)I2 * DIM);
#pragma unroll
            for (int i = 0; i < 16; i++) {
                float4 e1 = p1[i], e2 = p2[i];
                d1 = fmaf(xr[i].x, e1.x, d1); d1 = fmaf(xr[i].y, e1.y, d1);
                d1 = fmaf(xr[i].z, e1.z, d1); d1 = fmaf(xr[i].w, e1.w, d1);
                d2 = fmaf(xr[i].x, e2.x, d2); d2 = fmaf(xr[i].y, e2.y, d2);
                d2 = fmaf(xr[i].z, e2.z, d2); d2 = fmaf(xr[i].w, e2.w, d2);
            }
            float s1 = fmaf(-2.f, d1, esq_s[I1]);
            float s2 = fmaf(-2.f, d2, esq_s[I2]);
            if (s2 < s1 || (s2 == s1 && I2 < I1)) I1 = I2;
        }

        out[INDS_OFF + (size_t)row_g * KB + kb] = (float)I1;

        const float4* ep = reinterpret_cast<const float4*>(
            cbook + ((size_t)kb * CB + I1) * DIM);
        float4* op = reinterpret_cast<float4*>(
            out + (size_t)row_g * D_FULL + kb * DIM);
#pragma unroll
        for (int i = 0; i < 16; i++) {
            float4 e = ep[i];
            op[i] = e;
            float dx = xr[i].x - e.x, dy = xr[i].y - e.y;
            float dz = xr[i].z - e.z, dw = xr[i].w - e.w;
            csum += dx * dx + dy * dy + dz * dz + dw * dw;
        }
    }

    // deterministic commit-partial block reduce
    float* s_red = reinterpret_cast<float*>(smem + SM_RED);
    s_red[t] = csum;
    __syncthreads();
    for (int s = NTHR / 2; s > 0; s >>= 1) {
        if (t < s) s_red[t] += s_red[t + s];
        __syncthreads();
    }
    if (t == 0) g_part[kb * NMT + mtb] = s_red[0];
}

// ---------------- kernel: commit reduce ----------------
__global__ void commit_reduce(float* __restrict__ out) {
    __shared__ float s[NMT];
    const int kb = blockIdx.x;
    const int t  = threadIdx.x;      // 64 threads
    s[t] = g_part[kb * NMT + t];
    __syncthreads();
    for (int st = NMT / 2; st > 0; st >>= 1) {
        if (t < st) s[t] += s[t + st];
        __syncthreads();
    }
    if (t == 0)
        out[COMMIT_OFF + kb] = s[0] * (1.0f / (float)(ROWS * DIM));
}

extern "C" void kernel_launch(void* const* d_in, const int* in_sizes, int n_in,
                              void* d_out, int out_size) {
    const float* x  = (const float*)d_in[0];   // [4,2048,512]
    const float* cb = (const float*)d_in[1];   // [8,1024,64]
    float* out = (float*)d_out;
    (void)in_sizes; (void)n_in; (void)out_size;

    cudaFuncSetAttribute(vq_mma_kernel,
                         cudaFuncAttributeMaxDynamicSharedMemorySize, SM_TOTAL);

    esq_kernel<<<(KB * CB) / 128, 128>>>(cb);
    split_cb_kernel<<<(KB * CB * DIM) / 256, 256>>>(cb);
    vq_mma_kernel<<<dim3(NMT, KB), NTHR, SM_TOTAL>>>(x, cb, out);
    commit_reduce<<<KB, NMT>>>(out);
}